// round 2
// baseline (speedup 1.0000x reference)
#include <cuda_runtime.h>
#include <math.h>

// Problem constants (from reference): T=128, B=4096, NOBS=32
#define T_DIM   128
#define B_DIM   4096
#define NOBS    32
#define LOG_2PI 1.8378770664093453

// Scratch accumulator (device global; no allocation allowed)
__device__ double g_accum;

__device__ __forceinline__ float softplus_f(float x) {
    // numerically stable softplus
    return fmaxf(x, 0.0f) + log1pf(expf(-fabsf(x)));
}

__global__ void init_kernel() {
    g_accum = 0.0;
}

__global__ void __launch_bounds__(256, 8)
reduce_kernel(const float4* __restrict__ Y,
              const float4* __restrict__ Yh,
              const float*  __restrict__ raw_sn,
              int n4)
{
    const int tid    = blockIdx.x * blockDim.x + threadIdx.x;
    const int stride = gridDim.x * blockDim.x;   // multiple of 8 -> fixed channel quad

    // Each float4 group g covers channels (4g)&31 .. +3; since stride % 8 == 0,
    // the channel quad is fixed per thread.
    const int c = (tid & 7) * 4;
    const float iv0 = 1.0f / softplus_f(raw_sn[c + 0]);
    const float iv1 = 1.0f / softplus_f(raw_sn[c + 1]);
    const float iv2 = 1.0f / softplus_f(raw_sn[c + 2]);
    const float iv3 = 1.0f / softplus_f(raw_sn[c + 3]);

    float s = 0.0f;
    for (int g = tid; g < n4; g += stride) {
        float4 y  = Y[g];
        float4 yh = Yh[g];
        float d0 = yh.x - y.x;
        float d1 = yh.y - y.y;
        float d2 = yh.z - y.z;
        float d3 = yh.w - y.w;
        s = fmaf(d0 * d0, iv0, s);
        s = fmaf(d1 * d1, iv1, s);
        s = fmaf(d2 * d2, iv2, s);
        s = fmaf(d3 * d3, iv3, s);
    }

    // warp reduce
    #pragma unroll
    for (int off = 16; off > 0; off >>= 1)
        s += __shfl_down_sync(0xFFFFFFFFu, s, off);

    __shared__ float warp_sums[8];
    const int lane = threadIdx.x & 31;
    const int wid  = threadIdx.x >> 5;
    if (lane == 0) warp_sums[wid] = s;
    __syncthreads();

    if (wid == 0) {
        float v = (lane < (blockDim.x >> 5)) ? warp_sums[lane] : 0.0f;
        #pragma unroll
        for (int off = 4; off > 0; off >>= 1)
            v += __shfl_down_sync(0xFFFFFFFFu, v, off);
        if (lane == 0)
            atomicAdd(&g_accum, (double)v);
    }
}

__global__ void finalize_kernel(const float* __restrict__ raw_sn,
                                const float* __restrict__ kl,
                                const int*   __restrict__ Np,
                                float* __restrict__ out)
{
    // one warp: compute logdet = sum_i log(softplus(raw_sn[i]))
    int lane = threadIdx.x & 31;
    float lv = logf(softplus_f(raw_sn[lane]));
    #pragma unroll
    for (int off = 16; off > 0; off >>= 1)
        lv += __shfl_down_sync(0xFFFFFFFFu, lv, off);

    if (lane == 0) {
        double S      = g_accum;
        double logdet = (double)lv;
        double Nd     = (double)(*Np);
        // result = 0.5*N*( S/B + T*(logdet + NOBS*log2pi) ) + kl
        double res = 0.5 * Nd * (S / (double)B_DIM +
                                 (double)T_DIM * (logdet + (double)NOBS * LOG_2PI))
                   + (double)(*kl);
        out[0] = (float)res;
    }
}

extern "C" void kernel_launch(void* const* d_in, const int* in_sizes, int n_in,
                              void* d_out, int out_size)
{
    const float* Y      = (const float*)d_in[0];
    const float* Yh     = (const float*)d_in[1];
    const float* raw_sn = (const float*)d_in[2];
    const float* kl     = (const float*)d_in[3];
    const int*   Np     = (const int*)d_in[4];
    float* out = (float*)d_out;

    const int n4 = (T_DIM * B_DIM * NOBS) / 4;  // 4,194,304 float4 groups

    init_kernel<<<1, 1>>>();
    reduce_kernel<<<1184, 256>>>((const float4*)Y, (const float4*)Yh, raw_sn, n4);
    finalize_kernel<<<1, 32>>>(raw_sn, kl, Np, out);
}